// round 14
// baseline (speedup 1.0000x reference)
#include <cuda_runtime.h>
#include <cstdint>

#define M_DIM 8192
#define N_DIM 8192
#define C_DIM 80

// R[c][n] = base[n] - pre_cls[n][c]   (2.6 MB; rows L1/L2-resident)
// out[m][:] = R[gt[m]][:]  (gather-broadcast copy).
__device__ float g_R[C_DIM * N_DIM];

// ---------------------------------------------------------------------------
// Kernel A: build R. 512 blocks x 16 n-rows x 256 threads (~1-2 us exposed).
// Coalesced float4 loads into shared, softplus with 16 threads/row (5 c's
// each) + subwarp shfl reduce, fast-math (tol 1e-3, we sit ~6e-8).
// ---------------------------------------------------------------------------
#define TN   16
#define SPAD 88

__global__ __launch_bounds__(256)
void build_R_kernel(const float* __restrict__ pre)
{
    __shared__ float S[TN * SPAD];
    __shared__ float base_sm[TN];

    const int tid = threadIdx.x;
    const int n0  = blockIdx.x * TN;

    // Coalesced load: 16 rows x 80 floats = 320 float4 (contiguous 5 KB).
    const float4* src = (const float4*)(pre + (size_t)n0 * C_DIM);
#pragma unroll
    for (int i = tid; i < TN * C_DIM / 4; i += 256) {
        float4 v = src[i];
        int l = 4 * i;
        *(float4*)&S[(l / C_DIM) * SPAD + (l % C_DIM)] = v;
    }
    __syncthreads();

    // Softplus: 16 threads per row, 5 c's each, 16-lane shfl reduce.
    {
        const int r = tid >> 4;        // row 0..15
        const int q = tid & 15;        // subthread 0..15
        float s = 0.0f;
#pragma unroll
        for (int i = 0; i < 5; ++i) {
            float x = S[r * SPAD + q * 5 + i];
            s += fmaxf(x, 0.0f) + __logf(1.0f + __expf(-fabsf(x)));
        }
        s += __shfl_xor_sync(0xffffffffu, s, 8);
        s += __shfl_xor_sync(0xffffffffu, s, 4);
        s += __shfl_xor_sync(0xffffffffu, s, 2);
        s += __shfl_xor_sync(0xffffffffu, s, 1);
        if (q == 0) base_sm[r] = s;
    }
    __syncthreads();

    // R[c][n0+k] = base[k] - S[k][c]; 16-float coalesced runs per c.
#pragma unroll
    for (int j = tid; j < C_DIM * TN; j += 256) {
        int c = j >> 4;
        int k = j & 15;
        g_R[(size_t)c * N_DIM + n0 + k] = base_sm[k] - S[k * SPAD + c];
    }
}

// ---------------------------------------------------------------------------
// Kernel B: out[m][n] = R[gt[m]][n].  (R13 writer, ONE change: plain .wb
// stores instead of __stcs — let L2 accumulate the write stream and batch
// writebacks into large, page-ordered DRAM bursts. The R12 transpose
// experiment showed DRAM write-page locality is the binding resource; the
// 2.6 MB read stream lives mostly in L1 and is insensitive to L2 occupancy.)
// grid (8 n-chunks, 1024 m-groups): consecutive block-ids cover all 8
// n-chunks of one m-group -> 256 KB contiguous writes per scheduling
// neighborhood. __ldg reads, 8 loads batched before the store burst.
// ---------------------------------------------------------------------------
#define BTHREADS 256
#define MROWS    8
#define N4       (N_DIM / 4)     // 2048 float4 per row

__global__ __launch_bounds__(BTHREADS)
void out_kernel(const int* __restrict__ gt, float4* __restrict__ out)
{
    const int n4 = blockIdx.x * BTHREADS + threadIdx.x;
    const int m0 = blockIdx.y * MROWS;

    __shared__ int sg[MROWS];
    if (threadIdx.x < MROWS) sg[threadIdx.x] = __ldg(&gt[m0 + threadIdx.x]);
    __syncthreads();

    float4 v[MROWS];
#pragma unroll
    for (int r = 0; r < MROWS; ++r)
        v[r] = __ldg((const float4*)(g_R + (size_t)sg[r] * N_DIM) + n4);

#pragma unroll
    for (int r = 0; r < MROWS; ++r)
        out[(size_t)(m0 + r) * N4 + n4] = v[r];   // plain .wb store
}

// ---------------------------------------------------------------------------
extern "C" void kernel_launch(void* const* d_in, const int* in_sizes, int n_in,
                              void* d_out, int out_size)
{
    const int*   gt  = (const int*)d_in[0];      // gt_kind_ind [M]
    const float* pre = (const float*)d_in[1];    // pre_cls [N, C]
    float4*      out = (float4*)d_out;           // [M, N] f32

    build_R_kernel<<<N_DIM / TN, 256>>>(pre);    // 512 blocks

    dim3 grid(N4 / BTHREADS, M_DIM / MROWS);     // (8, 1024)
    out_kernel<<<grid, BTHREADS>>>(gt, out);
}

// round 15
// speedup vs baseline: 1.6122x; 1.6122x over previous
#include <cuda_runtime.h>
#include <cstdint>

#define M_DIM 8192
#define N_DIM 8192
#define C_DIM 80

// R[c][n] = base[n] - pre_cls[n][c]   (2.6 MB; rows L1/L2-resident)
// out[m][:] = R[gt[m]][:]  (gather-broadcast copy).
__device__ float g_R[C_DIM * N_DIM];

// ---------------------------------------------------------------------------
// Kernel A: build R. 512 blocks x 16 n-rows x 256 threads (~1-2 us exposed).
// Coalesced float4 loads into shared, softplus with 16 threads/row (5 c's
// each) + subwarp shfl reduce, fast-math (tol 1e-3, we sit ~6e-8).
// ---------------------------------------------------------------------------
#define TN   16
#define SPAD 88

__global__ __launch_bounds__(256)
void build_R_kernel(const float* __restrict__ pre)
{
    __shared__ float S[TN * SPAD];
    __shared__ float base_sm[TN];

    const int tid = threadIdx.x;
    const int n0  = blockIdx.x * TN;

    // Coalesced load: 16 rows x 80 floats = 320 float4 (contiguous 5 KB).
    const float4* src = (const float4*)(pre + (size_t)n0 * C_DIM);
#pragma unroll
    for (int i = tid; i < TN * C_DIM / 4; i += 256) {
        float4 v = src[i];
        int l = 4 * i;
        *(float4*)&S[(l / C_DIM) * SPAD + (l % C_DIM)] = v;
    }
    __syncthreads();

    // Softplus: 16 threads per row, 5 c's each, 16-lane shfl reduce.
    {
        const int r = tid >> 4;        // row 0..15
        const int q = tid & 15;        // subthread 0..15
        float s = 0.0f;
#pragma unroll
        for (int i = 0; i < 5; ++i) {
            float x = S[r * SPAD + q * 5 + i];
            s += fmaxf(x, 0.0f) + __logf(1.0f + __expf(-fabsf(x)));
        }
        s += __shfl_xor_sync(0xffffffffu, s, 8);
        s += __shfl_xor_sync(0xffffffffu, s, 4);
        s += __shfl_xor_sync(0xffffffffu, s, 2);
        s += __shfl_xor_sync(0xffffffffu, s, 1);
        if (q == 0) base_sm[r] = s;
    }
    __syncthreads();

    // R[c][n0+k] = base[k] - S[k][c]; 16-float coalesced runs per c.
#pragma unroll
    for (int j = tid; j < C_DIM * TN; j += 256) {
        int c = j >> 4;
        int k = j & 15;
        g_R[(size_t)c * N_DIM + n0 + k] = base_sm[k] - S[k * SPAD + c];
    }
}

// ---------------------------------------------------------------------------
// Kernel B: out[m][n] = R[gt[m]][n].  (measured-optimal writer — R13)
// grid (8 n-chunks, 1024 m-groups): consecutive block-ids cover all 8
// n-chunks of one m-group -> each scheduling neighborhood writes a 256 KB
// contiguous output region (DRAM write-page locality is the binding
// resource, per the R12 transpose experiment). __ldg reads (L1-allocating:
// only 80 distinct 32 KB rows -> high hit rate; beats __ldcg by ~2 us).
// __stcs streaming stores (beats .wb by 22 us — .wb write-allocate evicts
// g_R from L2 and wrecks writeback ordering). 8 loads batched before the
// store burst for MLP.
// ---------------------------------------------------------------------------
#define BTHREADS 256
#define MROWS    8
#define N4       (N_DIM / 4)     // 2048 float4 per row

__global__ __launch_bounds__(BTHREADS)
void out_kernel(const int* __restrict__ gt, float4* __restrict__ out)
{
    const int n4 = blockIdx.x * BTHREADS + threadIdx.x;
    const int m0 = blockIdx.y * MROWS;

    __shared__ int sg[MROWS];
    if (threadIdx.x < MROWS) sg[threadIdx.x] = __ldg(&gt[m0 + threadIdx.x]);
    __syncthreads();

    float4 v[MROWS];
#pragma unroll
    for (int r = 0; r < MROWS; ++r)
        v[r] = __ldg((const float4*)(g_R + (size_t)sg[r] * N_DIM) + n4);

#pragma unroll
    for (int r = 0; r < MROWS; ++r)
        __stcs(&out[(size_t)(m0 + r) * N4 + n4], v[r]);
}

// ---------------------------------------------------------------------------
extern "C" void kernel_launch(void* const* d_in, const int* in_sizes, int n_in,
                              void* d_out, int out_size)
{
    const int*   gt  = (const int*)d_in[0];      // gt_kind_ind [M]
    const float* pre = (const float*)d_in[1];    // pre_cls [N, C]
    float4*      out = (float4*)d_out;           // [M, N] f32

    build_R_kernel<<<N_DIM / TN, 256>>>(pre);    // 512 blocks

    dim3 grid(N4 / BTHREADS, M_DIM / MROWS);     // (8, 1024)
    out_kernel<<<grid, BTHREADS>>>(gt, out);
}